// round 2
// baseline (speedup 1.0000x reference)
#include <cuda_runtime.h>

#define T_TOK 16384
#define NE    8
#define DIN   1024
#define DOUT  1024
#define NA    8
#define RANK  16
#define BM    128
#define MAX_TILES 144   // T/BM + E padding for boundary tiles

// ---------------- device scratch (no allocations allowed) ----------------
__device__ int   g_num_tiles;
__device__ int   g_tile_row[MAX_TILES];
__device__ int   g_tile_exp[MAX_TILES];
__device__ int   g_tile_rows[MAX_TILES];
__device__ float g_inter[T_TOK * RANK];   // 1 MB scratch: x @ lora_A

// ---------------- kernel 0: routing setup ----------------
__global__ void setup_kernel(const int* __restrict__ gs) {
    int off[NE + 1];
    off[0] = 0;
    for (int e = 0; e < NE; e++) off[e + 1] = off[e] + gs[e];
    int cnt = 0;
    for (int e = 0; e < NE; e++) {
        for (int s = off[e]; s < off[e + 1]; s += BM) {
            g_tile_row[cnt]  = s;
            g_tile_exp[cnt]  = e;
            g_tile_rows[cnt] = min(BM, off[e + 1] - s);
            cnt++;
        }
    }
    g_num_tiles = cnt;
}

// ---------------- kernel 1: inter = x @ lora_A[a_t, e_t]  -> [T, R] ----------------
__global__ __launch_bounds__(256) void lora_inter_kernel(
    const float* __restrict__ x,
    const int*   __restrict__ adap,
    const float* __restrict__ lA)
{
    __shared__ float xs[BM][33];            // padded: avoids bank conflicts on [tok][kk]
    __shared__ float as_[NA][32][RANK];

    int tile = blockIdx.x;
    if (tile >= g_num_tiles) return;
    int row0 = g_tile_row[tile];
    int e    = g_tile_exp[tile];
    int rows = g_tile_rows[tile];
    int tid  = threadIdx.x;
    int r    = tid & 15;        // rank column
    int tg   = tid >> 4;        // token group 0..15; tokens tg + 16*j

    int   aj[8];
    float acc[8];
#pragma unroll
    for (int j = 0; j < 8; j++) {
        int tok = tg + j * 16;
        aj[j]  = (tok < rows) ? adap[row0 + tok] : 0;
        acc[j] = 0.f;
    }

    for (int k0 = 0; k0 < DIN; k0 += 32) {
#pragma unroll
        for (int it = 0; it < 4; it++) {       // load 128x32 x-chunk
            int flat = (tid + it * 256) * 4;
            int tok  = flat >> 5;
            int kk   = flat & 31;
            float4 v = make_float4(0.f, 0.f, 0.f, 0.f);
            if (tok < rows) v = *(const float4*)&x[(row0 + tok) * DIN + k0 + kk];
            xs[tok][kk] = v.x; xs[tok][kk + 1] = v.y;
            xs[tok][kk + 2] = v.z; xs[tok][kk + 3] = v.w;
        }
#pragma unroll
        for (int it = 0; it < 4; it++) {       // load all 8 adapters' A chunk [8][32][16]
            int flat = (tid + it * 256) * 4;
            int a    = flat >> 9;
            int rem  = flat & 511;
            int kk   = rem >> 4;
            int rr   = rem & 15;
            float4 v = *(const float4*)&lA[((size_t)(a * NE + e) * DIN + k0 + kk) * RANK + rr];
            *(float4*)&as_[a][kk][rr] = v;
        }
        __syncthreads();
#pragma unroll
        for (int kk = 0; kk < 32; kk++) {
#pragma unroll
            for (int j = 0; j < 8; j++) {
                acc[j] += xs[tg + j * 16][kk] * as_[aj[j]][kk][r];
            }
        }
        __syncthreads();
    }

#pragma unroll
    for (int j = 0; j < 8; j++) {
        int tok = tg + j * 16;
        if (tok < rows) g_inter[(row0 + tok) * RANK + r] = acc[j];
    }
}

// ---------------- kernel 2: base grouped GEMM + fused LoRA-B epilogue ----------------
// Tile: 128x128x16, 256 threads, 8x8 microtile.
// Dynamic smem is aliased: mainloop uses 16KB (As+Bs); epilogue reuses it for
// lora_B slices (64KB) + inter (8KB) + scales + adapter ids => ~74.3KB total.
#define SMEM_MAIN_BYTES ((NA * RANK * 128 + BM * RANK + 8) * 4 + BM * 4)

__global__ __launch_bounds__(256) void main_gemm_kernel(
    const float* __restrict__ x,
    const float* __restrict__ wgt,
    const float* __restrict__ lB,
    const float* __restrict__ lscale,
    const int*   __restrict__ adap,
    float*       __restrict__ out)
{
    extern __shared__ float smem[];
    int tile = blockIdx.x;
    if (tile >= g_num_tiles) return;
    int row0 = g_tile_row[tile];
    int e    = g_tile_exp[tile];
    int rows = g_tile_rows[tile];
    int col  = blockIdx.y * 128;
    int tid  = threadIdx.x;
    int tx   = tid & 15;       // 16 cols of 8
    int ty   = tid >> 4;       // 16 rows of 8

    float* As = smem;           // [16][128] x^T
    float* Bs = smem + 16 * 128;// [16][128] W

    float acc[8][8];
#pragma unroll
    for (int i = 0; i < 8; i++)
#pragma unroll
        for (int j = 0; j < 8; j++) acc[i][j] = 0.f;

    for (int k0 = 0; k0 < DIN; k0 += 16) {
#pragma unroll
        for (int it = 0; it < 2; it++) {     // x tile -> As transposed
            int m  = (tid >> 2) + it * 64;
            int kq = (tid & 3) * 4;
            float4 v = make_float4(0.f, 0.f, 0.f, 0.f);
            if (m < rows) v = *(const float4*)&x[(size_t)(row0 + m) * DIN + k0 + kq];
            As[(kq + 0) * 128 + m] = v.x;
            As[(kq + 1) * 128 + m] = v.y;
            As[(kq + 2) * 128 + m] = v.z;
            As[(kq + 3) * 128 + m] = v.w;
        }
#pragma unroll
        for (int it = 0; it < 2; it++) {     // W tile -> Bs
            int k  = (tid >> 5) + it * 8;
            int n4 = (tid & 31) * 4;
            float4 v = *(const float4*)&wgt[((size_t)e * DIN + k0 + k) * DOUT + col + n4];
            *(float4*)&Bs[k * 128 + n4] = v;
        }
        __syncthreads();
#pragma unroll
        for (int k = 0; k < 16; k++) {
            float4 a0 = *(float4*)&As[k * 128 + ty * 8];
            float4 a1 = *(float4*)&As[k * 128 + ty * 8 + 4];
            float4 b0 = *(float4*)&Bs[k * 128 + tx * 8];
            float4 b1 = *(float4*)&Bs[k * 128 + tx * 8 + 4];
            float av[8] = {a0.x, a0.y, a0.z, a0.w, a1.x, a1.y, a1.z, a1.w};
            float bv[8] = {b0.x, b0.y, b0.z, b0.w, b1.x, b1.y, b1.z, b1.w};
#pragma unroll
            for (int i = 0; i < 8; i++)
#pragma unroll
                for (int j = 0; j < 8; j++) acc[i][j] += av[i] * bv[j];
        }
        __syncthreads();
    }

    // ---- epilogue: acc += scale[a] * inter[m,:] @ lora_B[a,e][:, col:col+128] ----
    float* Bl      = smem;                         // [8][16][128]
    float* inter_s = smem + NA * RANK * 128;       // [128][16]
    float* scale_s = inter_s + BM * RANK;          // [8]
    int*   adap_s  = (int*)(scale_s + 8);          // [128]

#pragma unroll
    for (int it = 0; it < 16; it++) {              // 16384 floats of lora_B slices
        int flat = (tid + it * 256) * 4;
        int a    = flat >> 11;
        int rem  = flat & 2047;
        int r    = rem >> 7;
        int n    = rem & 127;
        *(float4*)&Bl[flat] =
            *(const float4*)&lB[((size_t)(a * NE + e) * RANK + r) * DOUT + col + n];
    }
#pragma unroll
    for (int it = 0; it < 2; it++) {               // inter tile
        int flat = (tid + it * 256) * 4;
        int m    = flat >> 4;
        float4 v = make_float4(0.f, 0.f, 0.f, 0.f);
        if (m < rows) v = *(const float4*)&g_inter[(row0 + m) * RANK + (flat & 15)];
        *(float4*)&inter_s[flat] = v;
    }
    if (tid < 8)   scale_s[tid] = lscale[tid];
    if (tid < 128) adap_s[tid]  = (tid < rows) ? adap[row0 + tid] : 0;
    __syncthreads();

#pragma unroll
    for (int i = 0; i < 8; i++) {
        int   m = ty * 8 + i;
        int   a = adap_s[m];
        float s = scale_s[a];
#pragma unroll
        for (int r = 0; r < RANK; r++) {
            float  wv = inter_s[m * RANK + r] * s;
            float4 b0 = *(float4*)&Bl[(a * RANK + r) * 128 + tx * 8];
            float4 b1 = *(float4*)&Bl[(a * RANK + r) * 128 + tx * 8 + 4];
            acc[i][0] += wv * b0.x; acc[i][1] += wv * b0.y;
            acc[i][2] += wv * b0.z; acc[i][3] += wv * b0.w;
            acc[i][4] += wv * b1.x; acc[i][5] += wv * b1.y;
            acc[i][6] += wv * b1.z; acc[i][7] += wv * b1.w;
        }
    }

#pragma unroll
    for (int i = 0; i < 8; i++) {
        int m = ty * 8 + i;
        if (m < rows) {
            float4 v0 = make_float4(acc[i][0], acc[i][1], acc[i][2], acc[i][3]);
            float4 v1 = make_float4(acc[i][4], acc[i][5], acc[i][6], acc[i][7]);
            float* p = &out[(size_t)(row0 + m) * DOUT + col + tx * 8];
            *(float4*)p       = v0;
            *(float4*)(p + 4) = v1;
        }
    }
}

// ---------------- launch ----------------
extern "C" void kernel_launch(void* const* d_in, const int* in_sizes, int n_in,
                              void* d_out, int out_size) {
    const float* x      = (const float*)d_in[0];
    const int*   gs     = (const int*)  d_in[1];
    const int*   adap   = (const int*)  d_in[2];
    const float* wgt    = (const float*)d_in[3];
    const float* lA     = (const float*)d_in[4];
    const float* lB     = (const float*)d_in[5];
    const float* lscale = (const float*)d_in[6];
    float*       out    = (float*)d_out;

    cudaFuncSetAttribute(main_gemm_kernel,
                         cudaFuncAttributeMaxDynamicSharedMemorySize,
                         SMEM_MAIN_BYTES);

    setup_kernel<<<1, 1>>>(gs);
    lora_inter_kernel<<<MAX_TILES, 256>>>(x, adap, lA);
    main_gemm_kernel<<<dim3(MAX_TILES, DOUT / 128), 256, SMEM_MAIN_BYTES>>>(
        x, wgt, lB, lscale, adap, out);
}

// round 4
// speedup vs baseline: 2.2068x; 2.2068x over previous
#include <cuda_runtime.h>
#include <cstdint>

#define T_TOK 16384
#define NE    8
#define DIN   1024
#define DOUT  1024
#define NA    8
#define RANK  16
#define BM    128
#define BN    128
#define BK    32
#define KLORA (NA * RANK)          // 128
#define KEXT  (DIN + KLORA)        // 1152
#define NCHUNK (KEXT / BK)         // 36
#define MAX_TILES 144
#define ASTRIDE 36                 // smem row stride in floats (32 + 4 pad)
#define ABYTES  (BM * ASTRIDE * 4) // 18432 per buffer
#define DSMEM_BYTES (4 * ABYTES)   // A0,A1,B0,B1 = 73728

// ---------------- device scratch (static, no allocations) ----------------
__device__ int   g_num_tiles;
__device__ int   g_tile_row[MAX_TILES];
__device__ int   g_tile_exp[MAX_TILES];
__device__ int   g_tile_rows[MAX_TILES];
__device__ float g_xe[(size_t)T_TOK * KEXT];      // 75.5 MB: [rna(x) | spread scaled inter]
__device__ float g_wt[(size_t)NE * DOUT * KEXT];  // 36 MB:   [e][n][k]: rna(W^T) | rna(lora_B)

// ---------------- helpers ----------------
__device__ __forceinline__ uint32_t smem_u32(const void* p) {
    uint32_t a;
    asm("{ .reg .u64 t; cvta.to.shared.u64 t, %1; cvt.u32.u64 %0, t; }" : "=r"(a) : "l"(p));
    return a;
}
__device__ __forceinline__ float rna_tf32(float x) {
    uint32_t y;
    asm("cvt.rna.tf32.f32 %0, %1;" : "=r"(y) : "f"(x));
    return __uint_as_float(y);
}
__device__ __forceinline__ void cp_async16(uint32_t dst, const void* src, int srcsize) {
    asm volatile("cp.async.cg.shared.global [%0], [%1], 16, %2;"
                 :: "r"(dst), "l"(src), "r"(srcsize) : "memory");
}

// ---------------- kernel 0: routing setup ----------------
__global__ void setup_kernel(const int* __restrict__ gs) {
    int off[NE + 1];
    off[0] = 0;
    for (int e = 0; e < NE; e++) off[e + 1] = off[e] + gs[e];
    int cnt = 0;
    for (int e = 0; e < NE; e++)
        for (int s = off[e]; s < off[e + 1]; s += BM) {
            g_tile_row[cnt]  = s;
            g_tile_exp[cnt]  = e;
            g_tile_rows[cnt] = min(BM, off[e + 1] - s);
            cnt++;
        }
    g_num_tiles = cnt;
}

// ---------------- kernel 1: W transpose + tf32 round ----------------
__global__ __launch_bounds__(256) void transpose_w_kernel(const float* __restrict__ wgt) {
    __shared__ float tile[32][33];
    int e  = blockIdx.z;
    int k0 = blockIdx.x * 32;
    int n0 = blockIdx.y * 32;
    int tx = threadIdx.x;          // 32
    int ty = threadIdx.y;          // 8
#pragma unroll
    for (int i = 0; i < 32; i += 8)
        tile[ty + i][tx] = wgt[((size_t)e * DIN + k0 + ty + i) * DOUT + n0 + tx];
    __syncthreads();
#pragma unroll
    for (int i = 0; i < 32; i += 8)
        g_wt[((size_t)e * DOUT + n0 + ty + i) * KEXT + k0 + tx] = rna_tf32(tile[tx][ty + i]);
}

// ---------------- kernel 2: Bext fill ----------------
__global__ __launch_bounds__(256) void lorab_fill_kernel(const float* __restrict__ lB) {
    int e  = blockIdx.x;
    int n0 = blockIdx.y * 128;
    for (int f = threadIdx.x; f < 128 * KLORA; f += 256) {
        int n = f >> 7;
        int j = f & 127;
        int a = j >> 4, r = j & 15;
        g_wt[((size_t)e * DOUT + n0 + n) * KEXT + DIN + j] =
            rna_tf32(lB[(((size_t)a * NE + e) * RANK + r) * DOUT + n0 + n]);
    }
}

// ---------------- kernel 3: g_xe[:, 0:1024] = rna(x) ----------------
__global__ __launch_bounds__(256) void xe_round_kernel(const float* __restrict__ x) {
    int tid = threadIdx.x;
#pragma unroll
    for (int s = 0; s < 4; s++) {
        size_t t = (size_t)blockIdx.x * 4 + s;
        float4 v = *(const float4*)&x[t * DIN + tid * 4];
        v.x = rna_tf32(v.x); v.y = rna_tf32(v.y);
        v.z = rna_tf32(v.z); v.w = rna_tf32(v.w);
        *(float4*)&g_xe[t * KEXT + tid * 4] = v;
    }
}

// ---------------- kernel 4: g_xe[:, 1024:1152] = spread(scale * (x @ lora_A)) ----------------
__global__ __launch_bounds__(256) void lora_inter_kernel(
    const float* __restrict__ x,
    const int*   __restrict__ adap,
    const float* __restrict__ lA,
    const float* __restrict__ lscale)
{
    __shared__ float xs[BM][33];
    __shared__ float as_[NA][32][RANK];

    int tile = blockIdx.x;
    if (tile >= g_num_tiles) return;
    int row0 = g_tile_row[tile];
    int e    = g_tile_exp[tile];
    int rows = g_tile_rows[tile];
    int tid  = threadIdx.x;
    int r    = tid & 15;
    int tg   = tid >> 4;

    int   aj[8];
    float acc[8];
#pragma unroll
    for (int j = 0; j < 8; j++) {
        int tok = tg + j * 16;
        aj[j]  = (tok < rows) ? adap[row0 + tok] : 0;
        acc[j] = 0.f;
    }

    for (int k0 = 0; k0 < DIN; k0 += 32) {
#pragma unroll
        for (int it = 0; it < 4; it++) {
            int flat = (tid + it * 256) * 4;
            int tok  = flat >> 5;
            int kk   = flat & 31;
            float4 v = make_float4(0.f, 0.f, 0.f, 0.f);
            if (tok < rows) v = *(const float4*)&x[(size_t)(row0 + tok) * DIN + k0 + kk];
            xs[tok][kk] = v.x; xs[tok][kk + 1] = v.y;
            xs[tok][kk + 2] = v.z; xs[tok][kk + 3] = v.w;
        }
#pragma unroll
        for (int it = 0; it < 4; it++) {
            int flat = (tid + it * 256) * 4;
            int a    = flat >> 9;
            int rem  = flat & 511;
            int kk   = rem >> 4;
            int rr   = rem & 15;
            float4 v = *(const float4*)&lA[((size_t)(a * NE + e) * DIN + k0 + kk) * RANK + rr];
            *(float4*)&as_[a][kk][rr] = v;
        }
        __syncthreads();
#pragma unroll
        for (int kk = 0; kk < 32; kk++)
#pragma unroll
            for (int j = 0; j < 8; j++)
                acc[j] += xs[tg + j * 16][kk] * as_[aj[j]][kk][r];
        __syncthreads();
    }

#pragma unroll
    for (int j = 0; j < 8; j++) {
        int tok = tg + j * 16;
        if (tok < rows) {
            float v = rna_tf32(acc[j] * lscale[aj[j]]);
            float* dst = g_xe + (size_t)(row0 + tok) * KEXT + DIN + r;
#pragma unroll
            for (int a = 0; a < NA; a++) dst[a * RANK] = (a == aj[j]) ? v : 0.f;
        }
    }
}

// ---------------- kernel 5: tf32 mma.sync GEMM, 128x128 tile, K = 1152 ----------------
__global__ __launch_bounds__(256) void main_gemm_kernel(float* __restrict__ out) {
    extern __shared__ char sm[];
    int tile = blockIdx.y;
    if (tile >= g_num_tiles) return;
    int row0 = g_tile_row[tile];
    int e    = g_tile_exp[tile];
    int rows = g_tile_rows[tile];
    int col0 = blockIdx.x * BN;
    int tid  = threadIdx.x;
    int lane = tid & 31;
    int wid  = tid >> 5;
    int wm   = (wid & 3) * 32;     // warp row base (4 warps in M)
    int wn   = (wid >> 2) * 64;    // warp col base (2 warps in N)
    int gi   = lane >> 2;          // groupID
    int ti   = lane & 3;           // threadID_in_group

    uint32_t sbase = smem_u32(sm);
    const float* arow = g_xe + (size_t)row0 * KEXT;
    const float* brow = g_wt + ((size_t)e * DOUT + col0) * KEXT;

    float acc[2][8][4];
#pragma unroll
    for (int i = 0; i < 2; i++)
#pragma unroll
        for (int j = 0; j < 8; j++)
#pragma unroll
            for (int q = 0; q < 4; q++) acc[i][j][q] = 0.f;

    // -------- async load of one K-chunk into buffer c&1 --------
    auto load_chunk = [&](int c) {
        uint32_t ab = sbase + (c & 1) * ABYTES;
        uint32_t bb = sbase + 2 * ABYTES + (c & 1) * ABYTES;
#pragma unroll
        for (int it = 0; it < 4; it++) {
            int f = tid + it * 256;           // 0..1023
            int m = f >> 3, q = f & 7;        // row, float4-within-row
            cp_async16(ab + m * (ASTRIDE * 4) + q * 16,
                       arow + (size_t)m * KEXT + c * BK + q * 4,
                       (m < rows) ? 16 : 0);
            cp_async16(bb + m * (ASTRIDE * 4) + q * 16,
                       brow + (size_t)m * KEXT + c * BK + q * 4, 16);
        }
    };

    load_chunk(0);
    asm volatile("cp.async.commit_group;" ::: "memory");

    for (int c = 0; c < NCHUNK; c++) {
        if (c + 1 < NCHUNK) {
            load_chunk(c + 1);
            asm volatile("cp.async.commit_group;" ::: "memory");
            asm volatile("cp.async.wait_group 1;" ::: "memory");
        } else {
            asm volatile("cp.async.wait_group 0;" ::: "memory");
        }
        __syncthreads();

        const uint32_t* As = (const uint32_t*)(sm + (c & 1) * ABYTES);
        const uint32_t* Bs = (const uint32_t*)(sm + 2 * ABYTES + (c & 1) * ABYTES);

#pragma unroll
        for (int t = 0; t < 4; t++) {          // 4 k-steps of 8
            uint32_t a[2][4], b[8][2];
#pragma unroll
            for (int i = 0; i < 2; i++) {
                int r0 = (wm + i * 16 + gi) * ASTRIDE + t * 8 + ti;
                a[i][0] = As[r0];
                a[i][1] = As[r0 + 8 * ASTRIDE];
                a[i][2] = As[r0 + 4];
                a[i][3] = As[r0 + 8 * ASTRIDE + 4];
            }
#pragma unroll
            for (int j = 0; j < 8; j++) {
                int r0 = (wn + j * 8 + gi) * ASTRIDE + t * 8 + ti;
                b[j][0] = Bs[r0];
                b[j][1] = Bs[r0 + 4];
            }
#pragma unroll
            for (int i = 0; i < 2; i++)
#pragma unroll
                for (int j = 0; j < 8; j++) {
                    float* d = acc[i][j];
                    asm volatile(
                        "mma.sync.aligned.m16n8k8.row.col.f32.tf32.tf32.f32 "
                        "{%0,%1,%2,%3}, {%4,%5,%6,%7}, {%8,%9}, {%0,%1,%2,%3};"
                        : "+f"(d[0]), "+f"(d[1]), "+f"(d[2]), "+f"(d[3])
                        : "r"(a[i][0]), "r"(a[i][1]), "r"(a[i][2]), "r"(a[i][3]),
                          "r"(b[j][0]), "r"(b[j][1]));
                }
        }
        __syncthreads();
    }

    // -------- epilogue: direct register -> gmem (no LoRA work left) --------
    float* obase = out + (size_t)row0 * DOUT + col0;
#pragma unroll
    for (int i = 0; i < 2; i++) {
        int r1 = wm + i * 16 + gi;
#pragma unroll
        for (int j = 0; j < 8; j++) {
            int cn = wn + j * 8 + ti * 2;
            if (r1 < rows)
                *(float2*)(obase + (size_t)r1 * DOUT + cn) =
                    make_float2(acc[i][j][0], acc[i][j][1]);
            if (r1 + 8 < rows)
                *(float2*)(obase + (size_t)(r1 + 8) * DOUT + cn) =
                    make_float2(acc[i][j][2], acc[i][j][3]);
        }
    }
}

// ---------------- launch ----------------
extern "C" void kernel_launch(void* const* d_in, const int* in_sizes, int n_in,
                              void* d_out, int out_size) {
    const float* x      = (const float*)d_in[0];
    const int*   gs     = (const int*)  d_in[1];
    const int*   adap   = (const int*)  d_in[2];
    const float* wgt    = (const float*)d_in[3];
    const float* lA     = (const float*)d_in[4];
    const float* lB     = (const float*)d_in[5];
    const float* lscale = (const float*)d_in[6];
    float*       out    = (float*)d_out;

    cudaFuncSetAttribute(main_gemm_kernel,
                         cudaFuncAttributeMaxDynamicSharedMemorySize, DSMEM_BYTES);

    setup_kernel<<<1, 1>>>(gs);
    transpose_w_kernel<<<dim3(DIN / 32, DOUT / 32, NE), dim3(32, 8)>>>(wgt);
    lorab_fill_kernel<<<dim3(NE, DOUT / 128), 256>>>(lB);
    xe_round_kernel<<<T_TOK / 4, 256>>>(x);
    lora_inter_kernel<<<MAX_TILES, 256>>>(x, adap, lA, lscale);
    main_gemm_kernel<<<dim3(DOUT / BN, MAX_TILES), 256, DSMEM_BYTES>>>(out);
}

// round 5
// speedup vs baseline: 3.0759x; 1.3938x over previous
#include <cuda_runtime.h>
#include <cuda_fp16.h>
#include <cstdint>

#define T_TOK 16384
#define NE    8
#define DIN   1024
#define DOUT  1024
#define NA    8
#define RANK  16
#define BM    128
#define BN    128
#define BK    64                    // halfs per K-chunk (128 bytes)
#define KLORA (NA * RANK)           // 128
#define KEXT  (DIN + KLORA)         // 1152
#define NCHUNK (KEXT / BK)          // 18
#define MAX_TILES 144
#define RSTRIDE 72                  // smem row stride in halfs (64 + 8 pad, 144B)
#define ABY   (BM * RSTRIDE * 2)    // 18432 bytes per buffer
#define DSMEM_BYTES (4 * ABY)       // A0,A1,B0,B1 = 73728

// ---------------- device scratch (static, no allocations) ----------------
__device__ int   g_num_tiles;
__device__ int   g_tile_row[MAX_TILES];
__device__ int   g_tile_exp[MAX_TILES];
__device__ int   g_tile_rows[MAX_TILES];
__device__ __align__(256) __half g_xe[(size_t)T_TOK * KEXT];     // 37.7 MB [rn(x) | spread scaled inter]
__device__ __align__(256) __half g_wt[(size_t)NE * DOUT * KEXT]; // 18.9 MB [e][n][k]: rn(W^T) | rn(lora_B)

// ---------------- helpers ----------------
__device__ __forceinline__ uint32_t smem_u32(const void* p) {
    uint32_t a;
    asm("{ .reg .u64 t; cvta.to.shared.u64 t, %1; cvt.u32.u64 %0, t; }" : "=r"(a) : "l"(p));
    return a;
}
__device__ __forceinline__ void cp_async16(uint32_t dst, const void* src, int srcsize) {
    asm volatile("cp.async.cg.shared.global [%0], [%1], 16, %2;"
                 :: "r"(dst), "l"(src), "r"(srcsize) : "memory");
}
__device__ __forceinline__ void ldsm_x4(uint32_t* r, uint32_t addr) {
    asm volatile("ldmatrix.sync.aligned.m8n8.x4.shared.b16 {%0,%1,%2,%3}, [%4];"
                 : "=r"(r[0]), "=r"(r[1]), "=r"(r[2]), "=r"(r[3]) : "r"(addr));
}

// ---------------- kernel 0: routing setup ----------------
__global__ void setup_kernel(const int* __restrict__ gs) {
    int off[NE + 1];
    off[0] = 0;
    for (int e = 0; e < NE; e++) off[e + 1] = off[e] + gs[e];
    int cnt = 0;
    for (int e = 0; e < NE; e++)
        for (int s = off[e]; s < off[e + 1]; s += BM) {
            g_tile_row[cnt]  = s;
            g_tile_exp[cnt]  = e;
            g_tile_rows[cnt] = min(BM, off[e + 1] - s);
            cnt++;
        }
    g_num_tiles = cnt;
}

// ---------------- kernel 1: W transpose + fp16 round ----------------
__global__ __launch_bounds__(256) void transpose_w_kernel(const float* __restrict__ wgt) {
    __shared__ float tile[32][33];
    int e  = blockIdx.z;
    int k0 = blockIdx.x * 32;
    int n0 = blockIdx.y * 32;
    int tx = threadIdx.x;          // 32
    int ty = threadIdx.y;          // 8
#pragma unroll
    for (int i = 0; i < 32; i += 8)
        tile[ty + i][tx] = wgt[((size_t)e * DIN + k0 + ty + i) * DOUT + n0 + tx];
    __syncthreads();
#pragma unroll
    for (int i = 0; i < 32; i += 8)
        g_wt[((size_t)e * DOUT + n0 + ty + i) * KEXT + k0 + tx] =
            __float2half_rn(tile[tx][ty + i]);
}

// ---------------- kernel 2: Bext fill ----------------
__global__ __launch_bounds__(256) void lorab_fill_kernel(const float* __restrict__ lB) {
    int e  = blockIdx.x;
    int n0 = blockIdx.y * 128;
    for (int f = threadIdx.x; f < 128 * KLORA; f += 256) {
        int n = f >> 7;
        int j = f & 127;
        int a = j >> 4, r = j & 15;
        g_wt[((size_t)e * DOUT + n0 + n) * KEXT + DIN + j] =
            __float2half_rn(lB[(((size_t)a * NE + e) * RANK + r) * DOUT + n0 + n]);
    }
}

// ---------------- kernel 3: g_xe[:, 0:1024] = rn_fp16(x) ----------------
__global__ __launch_bounds__(256) void xe_round_kernel(const float* __restrict__ x) {
    int tid = threadIdx.x;
#pragma unroll
    for (int s = 0; s < 4; s++) {
        size_t t = (size_t)blockIdx.x * 4 + s;
        float4 v = *(const float4*)&x[t * DIN + tid * 4];
        __half2 h0 = __floats2half2_rn(v.x, v.y);
        __half2 h1 = __floats2half2_rn(v.z, v.w);
        __half2* dst = (__half2*)&g_xe[t * KEXT + tid * 4];
        dst[0] = h0;
        dst[1] = h1;
    }
}

// ---------------- kernel 4: g_xe[:, 1024:1152] = spread(scale * (x @ lora_A)) ----------------
__global__ __launch_bounds__(256) void lora_inter_kernel(
    const float* __restrict__ x,
    const int*   __restrict__ adap,
    const float* __restrict__ lA,
    const float* __restrict__ lscale)
{
    __shared__ float xs[BM][33];
    __shared__ float as_[NA][32][RANK];

    int tile = blockIdx.x;
    if (tile >= g_num_tiles) return;
    int row0 = g_tile_row[tile];
    int e    = g_tile_exp[tile];
    int rows = g_tile_rows[tile];
    int tid  = threadIdx.x;
    int r    = tid & 15;
    int tg   = tid >> 4;

    int   aj[8];
    float acc[8];
#pragma unroll
    for (int j = 0; j < 8; j++) {
        int tok = tg + j * 16;
        aj[j]  = (tok < rows) ? adap[row0 + tok] : 0;
        acc[j] = 0.f;
    }

    for (int k0 = 0; k0 < DIN; k0 += 32) {
#pragma unroll
        for (int it = 0; it < 4; it++) {
            int flat = (tid + it * 256) * 4;
            int tok  = flat >> 5;
            int kk   = flat & 31;
            float4 v = make_float4(0.f, 0.f, 0.f, 0.f);
            if (tok < rows) v = *(const float4*)&x[(size_t)(row0 + tok) * DIN + k0 + kk];
            xs[tok][kk] = v.x; xs[tok][kk + 1] = v.y;
            xs[tok][kk + 2] = v.z; xs[tok][kk + 3] = v.w;
        }
#pragma unroll
        for (int it = 0; it < 4; it++) {
            int flat = (tid + it * 256) * 4;
            int a    = flat >> 9;
            int rem  = flat & 511;
            int kk   = rem >> 4;
            int rr   = rem & 15;
            float4 v = *(const float4*)&lA[((size_t)(a * NE + e) * DIN + k0 + kk) * RANK + rr];
            *(float4*)&as_[a][kk][rr] = v;
        }
        __syncthreads();
#pragma unroll
        for (int kk = 0; kk < 32; kk++)
#pragma unroll
            for (int j = 0; j < 8; j++)
                acc[j] += xs[tg + j * 16][kk] * as_[aj[j]][kk][r];
        __syncthreads();
    }

#pragma unroll
    for (int j = 0; j < 8; j++) {
        int tok = tg + j * 16;
        if (tok < rows) {
            __half hv = __float2half_rn(acc[j] * lscale[aj[j]]);
            __half hz = __float2half_rn(0.f);
            __half* dst = g_xe + (size_t)(row0 + tok) * KEXT + DIN + r;
#pragma unroll
            for (int a = 0; a < NA; a++) dst[a * RANK] = (a == aj[j]) ? hv : hz;
        }
    }
}

// ---------------- kernel 5: fp16 mma.sync GEMM, 128x128 tile, K = 1152 ----------------
__global__ __launch_bounds__(256) void main_gemm_kernel(float* __restrict__ out) {
    extern __shared__ char sm[];
    int tile = blockIdx.y;
    if (tile >= g_num_tiles) return;
    int row0 = g_tile_row[tile];
    int e    = g_tile_exp[tile];
    int rows = g_tile_rows[tile];
    int col0 = blockIdx.x * BN;
    int tid  = threadIdx.x;
    int lane = tid & 31;
    int wid  = tid >> 5;
    int wm   = (wid & 3) * 32;      // warp row base (4 warps in M)
    int wn   = (wid >> 2) * 64;     // warp col base (2 warps in N)
    int gi   = lane >> 2;           // groupID
    int ti   = lane & 3;            // threadID_in_group

    uint32_t sbase = smem_u32(sm);
    const __half* arow = g_xe + (size_t)row0 * KEXT;
    const __half* brow = g_wt + ((size_t)e * DOUT + col0) * KEXT;

    // ldmatrix per-lane byte offsets (within a buffer); k-step t adds t*32 bytes
    // A (x4): lanes 0-7 rows 0-7 k0 | 8-15 rows 8-15 k0 | 16-23 rows 0-7 k8 | 24-31 rows 8-15 k8
    uint32_t aoff[2];
#pragma unroll
    for (int i = 0; i < 2; i++)
        aoff[i] = (uint32_t)((wm + i * 16 + (lane & 15)) * RSTRIDE + (lane >> 4) * 8) * 2;
    // B (x4 over a j-pair p): lanes 0-7 n(j=2p) k0 | 8-15 n k8 | 16-23 n(j=2p+1) k0 | 24-31 k8
    uint32_t boff[4];
#pragma unroll
    for (int p = 0; p < 4; p++)
        boff[p] = (uint32_t)((wn + p * 16 + ((lane >> 4) << 3) + (lane & 7)) * RSTRIDE
                             + (((lane >> 3) & 1) << 3)) * 2;

    float acc[2][8][4];
#pragma unroll
    for (int i = 0; i < 2; i++)
#pragma unroll
        for (int j = 0; j < 8; j++)
#pragma unroll
            for (int q = 0; q < 4; q++) acc[i][j][q] = 0.f;

    auto load_chunk = [&](int c) {
        uint32_t ab = sbase + (c & 1) * ABY;
        uint32_t bb = sbase + 2 * ABY + (c & 1) * ABY;
#pragma unroll
        for (int it = 0; it < 4; it++) {
            int f = tid + it * 256;            // 0..1023
            int m = f >> 3, q = f & 7;         // row, 16B-chunk (8 halfs)
            cp_async16(ab + m * (RSTRIDE * 2) + q * 16,
                       arow + (size_t)m * KEXT + c * BK + q * 8,
                       (m < rows) ? 16 : 0);
            cp_async16(bb + m * (RSTRIDE * 2) + q * 16,
                       brow + (size_t)m * KEXT + c * BK + q * 8, 16);
        }
    };

    load_chunk(0);
    asm volatile("cp.async.commit_group;" ::: "memory");

    for (int c = 0; c < NCHUNK; c++) {
        if (c + 1 < NCHUNK) {
            load_chunk(c + 1);
            asm volatile("cp.async.commit_group;" ::: "memory");
            asm volatile("cp.async.wait_group 1;" ::: "memory");
        } else {
            asm volatile("cp.async.wait_group 0;" ::: "memory");
        }
        __syncthreads();

        uint32_t abase = sbase + (c & 1) * ABY;
        uint32_t bbase = sbase + 2 * ABY + (c & 1) * ABY;

#pragma unroll
        for (int t = 0; t < 4; t++) {           // 4 k-steps of 16
            uint32_t a[2][4], b[4][4];
#pragma unroll
            for (int i = 0; i < 2; i++) ldsm_x4(a[i], abase + aoff[i] + t * 32);
#pragma unroll
            for (int p = 0; p < 4; p++) ldsm_x4(b[p], bbase + boff[p] + t * 32);
#pragma unroll
            for (int i = 0; i < 2; i++)
#pragma unroll
                for (int j = 0; j < 8; j++) {
                    float* d = acc[i][j];
                    asm volatile(
                        "mma.sync.aligned.m16n8k16.row.col.f32.f16.f16.f32 "
                        "{%0,%1,%2,%3}, {%4,%5,%6,%7}, {%8,%9}, {%0,%1,%2,%3};"
                        : "+f"(d[0]), "+f"(d[1]), "+f"(d[2]), "+f"(d[3])
                        : "r"(a[i][0]), "r"(a[i][1]), "r"(a[i][2]), "r"(a[i][3]),
                          "r"(b[j >> 1][(j & 1) * 2]), "r"(b[j >> 1][(j & 1) * 2 + 1]));
                }
        }
        __syncthreads();
    }

    // -------- epilogue: registers -> gmem --------
    float* obase = out + (size_t)row0 * DOUT + col0;
#pragma unroll
    for (int i = 0; i < 2; i++) {
        int r1 = wm + i * 16 + gi;
#pragma unroll
        for (int j = 0; j < 8; j++) {
            int cn = wn + j * 8 + ti * 2;
            if (r1 < rows)
                *(float2*)(obase + (size_t)r1 * DOUT + cn) =
                    make_float2(acc[i][j][0], acc[i][j][1]);
            if (r1 + 8 < rows)
                *(float2*)(obase + (size_t)(r1 + 8) * DOUT + cn) =
                    make_float2(acc[i][j][2], acc[i][j][3]);
        }
    }
}

// ---------------- launch ----------------
extern "C" void kernel_launch(void* const* d_in, const int* in_sizes, int n_in,
                              void* d_out, int out_size) {
    const float* x      = (const float*)d_in[0];
    const int*   gs     = (const int*)  d_in[1];
    const int*   adap   = (const int*)  d_in[2];
    const float* wgt    = (const float*)d_in[3];
    const float* lA     = (const float*)d_in[4];
    const float* lB     = (const float*)d_in[5];
    const float* lscale = (const float*)d_in[6];
    float*       out    = (float*)d_out;

    cudaFuncSetAttribute(main_gemm_kernel,
                         cudaFuncAttributeMaxDynamicSharedMemorySize, DSMEM_BYTES);

    setup_kernel<<<1, 1>>>(gs);
    transpose_w_kernel<<<dim3(DIN / 32, DOUT / 32, NE), dim3(32, 8)>>>(wgt);
    lorab_fill_kernel<<<dim3(NE, DOUT / 128), 256>>>(lB);
    xe_round_kernel<<<T_TOK / 4, 256>>>(x);
    lora_inter_kernel<<<MAX_TILES, 256>>>(x, adap, lA, lscale);
    main_gemm_kernel<<<dim3(DOUT / BN, MAX_TILES), 256, DSMEM_BYTES>>>(out);
}

// round 7
// speedup vs baseline: 3.1014x; 1.0083x over previous
#include <cuda_runtime.h>
#include <cuda_fp16.h>
#include <cstdint>

#define T_TOK 16384
#define NE    8
#define DIN   1024
#define DOUT  1024
#define NA    8
#define RANK  16
#define BM    128
#define BN    128
#define BK    64                    // halfs per K-chunk (128 bytes)
#define KLORA (NA * RANK)           // 128
#define KEXT  (DIN + KLORA)         // 1152
#define NCHUNK (KEXT / BK)          // 18
#define MAX_TILES 144
#define RSTRIDE 72                  // smem row stride in halfs (64 + 8 pad, 144B)
#define ABY   (BM * RSTRIDE * 2)    // 18432 bytes per buffer
#define DSMEM_BYTES (4 * ABY)       // A0,A1,B0,B1 = 73728 (2 CTAs/SM: 147KB < 228KB)

// ---------------- device scratch (static, no allocations) ----------------
__device__ int   g_num_tiles;
__device__ int   g_tile_row[MAX_TILES];
__device__ int   g_tile_exp[MAX_TILES];
__device__ int   g_tile_rows[MAX_TILES];
__device__ __align__(256) __half g_xe[(size_t)T_TOK * KEXT];     // 37.7 MB [rn(x) | spread scaled inter]
__device__ __align__(256) __half g_wt[(size_t)NE * DOUT * KEXT]; // 18.9 MB [e][n][k]: rn(W^T) | rn(lora_B)

// ---------------- helpers ----------------
__device__ __forceinline__ uint32_t smem_u32(const void* p) {
    uint32_t a;
    asm("{ .reg .u64 t; cvta.to.shared.u64 t, %1; cvt.u32.u64 %0, t; }" : "=r"(a) : "l"(p));
    return a;
}
__device__ __forceinline__ void cp_async16(uint32_t dst, const void* src) {
    asm volatile("cp.async.cg.shared.global [%0], [%1], 16;"
                 :: "r"(dst), "l"(src) : "memory");
}
__device__ __forceinline__ void cp_async16p(uint32_t dst, const void* src, int srcsize) {
    asm volatile("cp.async.cg.shared.global [%0], [%1], 16, %2;"
                 :: "r"(dst), "l"(src), "r"(srcsize) : "memory");
}
__device__ __forceinline__ void ldsm_x4(uint32_t* r, uint32_t addr) {
    asm volatile("ldmatrix.sync.aligned.m8n8.x4.shared.b16 {%0,%1,%2,%3}, [%4];"
                 : "=r"(r[0]), "=r"(r[1]), "=r"(r[2]), "=r"(r[3]) : "r"(addr));
}

// ---------------- kernel 0: routing setup ----------------
__global__ void setup_kernel(const int* __restrict__ gs) {
    int off[NE + 1];
    off[0] = 0;
    for (int e = 0; e < NE; e++) off[e + 1] = off[e] + gs[e];
    int cnt = 0;
    for (int e = 0; e < NE; e++)
        for (int s = off[e]; s < off[e + 1]; s += BM) {
            g_tile_row[cnt]  = s;
            g_tile_exp[cnt]  = e;
            g_tile_rows[cnt] = min(BM, off[e + 1] - s);
            cnt++;
        }
    g_num_tiles = cnt;
}

// ---------------- kernel 1: W transpose + fp16 round ----------------
__global__ __launch_bounds__(256) void transpose_w_kernel(const float* __restrict__ wgt) {
    __shared__ float tile[32][33];
    int e  = blockIdx.z;
    int k0 = blockIdx.x * 32;
    int n0 = blockIdx.y * 32;
    int tx = threadIdx.x;          // 32
    int ty = threadIdx.y;          // 8
#pragma unroll
    for (int i = 0; i < 32; i += 8)
        tile[ty + i][tx] = wgt[((size_t)e * DIN + k0 + ty + i) * DOUT + n0 + tx];
    __syncthreads();
#pragma unroll
    for (int i = 0; i < 32; i += 8)
        g_wt[((size_t)e * DOUT + n0 + ty + i) * KEXT + k0 + tx] =
            __float2half_rn(tile[tx][ty + i]);
}

// ---------------- kernel 2: Bext fill ----------------
__global__ __launch_bounds__(256) void lorab_fill_kernel(const float* __restrict__ lB) {
    int e  = blockIdx.x;
    int n0 = blockIdx.y * 128;
    for (int f = threadIdx.x; f < 128 * KLORA; f += 256) {
        int n = f >> 7;
        int j = f & 127;
        int a = j >> 4, r = j & 15;
        g_wt[((size_t)e * DOUT + n0 + n) * KEXT + DIN + j] =
            __float2half_rn(lB[(((size_t)a * NE + e) * RANK + r) * DOUT + n0 + n]);
    }
}

// ---------------- kernel 3: g_xe[:, 0:1024] = rn_fp16(x) ----------------
__global__ __launch_bounds__(256) void xe_round_kernel(const float* __restrict__ x) {
    int tid = threadIdx.x;
#pragma unroll
    for (int s = 0; s < 4; s++) {
        size_t t = (size_t)blockIdx.x * 4 + s;
        float4 v = *(const float4*)&x[t * DIN + tid * 4];
        __half2 h0 = __floats2half2_rn(v.x, v.y);
        __half2 h1 = __floats2half2_rn(v.z, v.w);
        __half2* dst = (__half2*)&g_xe[t * KEXT + tid * 4];
        dst[0] = h0;
        dst[1] = h1;
    }
}

// ---------------- kernel 4: g_xe[:, 1024:1152] = spread(scale * (x @ lora_A)) ----------------
__global__ __launch_bounds__(256) void lora_inter_kernel(
    const float* __restrict__ x,
    const int*   __restrict__ adap,
    const float* __restrict__ lA,
    const float* __restrict__ lscale)
{
    __shared__ float xs[BM][33];
    __shared__ float as_[NA][32][RANK];

    int tile = blockIdx.x;
    if (tile >= g_num_tiles) return;
    int row0 = g_tile_row[tile];
    int e    = g_tile_exp[tile];
    int rows = g_tile_rows[tile];
    int tid  = threadIdx.x;
    int r    = tid & 15;
    int tg   = tid >> 4;

    int   aj[8];
    float acc[8];
#pragma unroll
    for (int j = 0; j < 8; j++) {
        int tok = tg + j * 16;
        aj[j]  = (tok < rows) ? adap[row0 + tok] : 0;
        acc[j] = 0.f;
    }

    for (int k0 = 0; k0 < DIN; k0 += 32) {
#pragma unroll
        for (int it = 0; it < 4; it++) {
            int flat = (tid + it * 256) * 4;
            int tok  = flat >> 5;
            int kk   = flat & 31;
            float4 v = make_float4(0.f, 0.f, 0.f, 0.f);
            if (tok < rows) v = *(const float4*)&x[(size_t)(row0 + tok) * DIN + k0 + kk];
            xs[tok][kk] = v.x; xs[tok][kk + 1] = v.y;
            xs[tok][kk + 2] = v.z; xs[tok][kk + 3] = v.w;
        }
#pragma unroll
        for (int it = 0; it < 4; it++) {
            int flat = (tid + it * 256) * 4;
            int a    = flat >> 9;
            int rem  = flat & 511;
            int kk   = rem >> 4;
            int rr   = rem & 15;
            float4 v = *(const float4*)&lA[((size_t)(a * NE + e) * DIN + k0 + kk) * RANK + rr];
            *(float4*)&as_[a][kk][rr] = v;
        }
        __syncthreads();
#pragma unroll
        for (int kk = 0; kk < 32; kk++)
#pragma unroll
            for (int j = 0; j < 8; j++)
                acc[j] += xs[tg + j * 16][kk] * as_[aj[j]][kk][r];
        __syncthreads();
    }

#pragma unroll
    for (int j = 0; j < 8; j++) {
        int tok = tg + j * 16;
        if (tok < rows) {
            __half hv = __float2half_rn(acc[j] * lscale[aj[j]]);
            __half hz = __float2half_rn(0.f);
            __half* dst = g_xe + (size_t)(row0 + tok) * KEXT + DIN + r;
#pragma unroll
            for (int a = 0; a < NA; a++) dst[a * RANK] = (a == aj[j]) ? hv : hz;
        }
    }
}

// ---------------- kernel 5: fp16 mma.sync GEMM, 128x128 tile, K = 1152 ----------------
// 2 CTAs/SM (4 warps/SMSP) + single __syncthreads per K-chunk.
__global__ __launch_bounds__(256, 2) void main_gemm_kernel(float* __restrict__ out) {
    extern __shared__ char sm[];
    int tile = blockIdx.y;
    if (tile >= g_num_tiles) return;
    int row0 = g_tile_row[tile];
    int e    = g_tile_exp[tile];
    int rows = g_tile_rows[tile];
    int col0 = blockIdx.x * BN;
    int tid  = threadIdx.x;
    int lane = tid & 31;
    int wid  = tid >> 5;
    int wm   = (wid & 3) * 32;      // warp row base (4 warps in M)
    int wn   = (wid >> 2) * 64;     // warp col base (2 warps in N)
    int gi   = lane >> 2;           // groupID
    int ti   = lane & 3;            // threadID_in_group

    uint32_t sbase = smem_u32(sm);
    const __half* arow = g_xe + (size_t)row0 * KEXT;
    const __half* brow = g_wt + ((size_t)e * DOUT + col0) * KEXT;

    // ldmatrix per-lane byte offsets (within a buffer); k-step t adds t*32 bytes
    uint32_t aoff[2];
#pragma unroll
    for (int i = 0; i < 2; i++)
        aoff[i] = (uint32_t)((wm + i * 16 + (lane & 15)) * RSTRIDE + (lane >> 4) * 8) * 2;
    uint32_t boff[4];
#pragma unroll
    for (int p = 0; p < 4; p++)
        boff[p] = (uint32_t)((wn + p * 16 + ((lane >> 4) << 3) + (lane & 7)) * RSTRIDE
                             + (((lane >> 3) & 1) << 3)) * 2;

    float acc[2][8][4];
#pragma unroll
    for (int i = 0; i < 2; i++)
#pragma unroll
        for (int j = 0; j < 8; j++)
#pragma unroll
            for (int q = 0; q < 4; q++) acc[i][j][q] = 0.f;

    // per-thread load coordinates (hoisted)
    bool full = (rows == BM);
    auto load_chunk = [&](int c) {
        uint32_t ab = sbase + (c & 1) * ABY;
        uint32_t bb = sbase + 2 * ABY + (c & 1) * ABY;
        if (full) {
#pragma unroll
            for (int it = 0; it < 4; it++) {
                int f = tid + it * 256;
                int m = f >> 3, q = f & 7;
                cp_async16(ab + m * (RSTRIDE * 2) + q * 16,
                           arow + (size_t)m * KEXT + c * BK + q * 8);
                cp_async16(bb + m * (RSTRIDE * 2) + q * 16,
                           brow + (size_t)m * KEXT + c * BK + q * 8);
            }
        } else {
#pragma unroll
            for (int it = 0; it < 4; it++) {
                int f = tid + it * 256;
                int m = f >> 3, q = f & 7;
                cp_async16p(ab + m * (RSTRIDE * 2) + q * 16,
                            arow + (size_t)m * KEXT + c * BK + q * 8,
                            (m < rows) ? 16 : 0);
                cp_async16(bb + m * (RSTRIDE * 2) + q * 16,
                           brow + (size_t)m * KEXT + c * BK + q * 8);
            }
        }
    };

    load_chunk(0);
    asm volatile("cp.async.commit_group;" ::: "memory");

    for (int c = 0; c < NCHUNK; c++) {
        // buffer c ready; sync also retires compute(c-1)'s reads of buffer c^1
        asm volatile("cp.async.wait_group 0;" ::: "memory");
        __syncthreads();

        if (c + 1 < NCHUNK) {
            load_chunk(c + 1);                        // fills buffer c^1, overlaps compute(c)
            asm volatile("cp.async.commit_group;" ::: "memory");
        }

        uint32_t abase = sbase + (c & 1) * ABY;
        uint32_t bbase = sbase + 2 * ABY + (c & 1) * ABY;

#pragma unroll
        for (int t = 0; t < 4; t++) {                 // 4 k-steps of 16
            uint32_t a[2][4], b[4][4];
#pragma unroll
            for (int i = 0; i < 2; i++) ldsm_x4(a[i], abase + aoff[i] + t * 32);
#pragma unroll
            for (int p = 0; p < 4; p++) ldsm_x4(b[p], bbase + boff[p] + t * 32);
#pragma unroll
            for (int i = 0; i < 2; i++)
#pragma unroll
                for (int j = 0; j < 8; j++) {
                    float* d = acc[i][j];
                    asm volatile(
                        "mma.sync.aligned.m16n8k16.row.col.f32.f16.f16.f32 "
                        "{%0,%1,%2,%3}, {%4,%5,%6,%7}, {%8,%9}, {%0,%1,%2,%3};"
                        : "+f"(d[0]), "+f"(d[1]), "+f"(d[2]), "+f"(d[3])
                        : "r"(a[i][0]), "r"(a[i][1]), "r"(a[i][2]), "r"(a[i][3]),
                          "r"(b[j >> 1][(j & 1) * 2]), "r"(b[j >> 1][(j & 1) * 2 + 1]));
                }
        }
    }

    // -------- epilogue: registers -> gmem --------
    float* obase = out + (size_t)row0 * DOUT + col0;
#pragma unroll
    for (int i = 0; i < 2; i++) {
        int r1 = wm + i * 16 + gi;
#pragma unroll
        for (int j = 0; j < 8; j++) {
            int cn = wn + j * 8 + ti * 2;
            if (r1 < rows)
                *(float2*)(obase + (size_t)r1 * DOUT + cn) =
                    make_float2(acc[i][j][0], acc[i][j][1]);
            if (r1 + 8 < rows)
                *(float2*)(obase + (size_t)(r1 + 8) * DOUT + cn) =
                    make_float2(acc[i][j][2], acc[i][j][3]);
        }
    }
}

// ---------------- launch ----------------
extern "C" void kernel_launch(void* const* d_in, const int* in_sizes, int n_in,
                              void* d_out, int out_size) {
    const float* x      = (const float*)d_in[0];
    const int*   gs     = (const int*)  d_in[1];
    const int*   adap   = (const int*)  d_in[2];
    const float* wgt    = (const float*)d_in[3];
    const float* lA     = (const float*)d_in[4];
    const float* lB     = (const float*)d_in[5];
    const float* lscale = (const float*)d_in[6];
    float*       out    = (float*)d_out;

    cudaFuncSetAttribute(main_gemm_kernel,
                         cudaFuncAttributeMaxDynamicSharedMemorySize, DSMEM_BYTES);

    setup_kernel<<<1, 1>>>(gs);
    transpose_w_kernel<<<dim3(DIN / 32, DOUT / 32, NE), dim3(32, 8)>>>(wgt);
    lorab_fill_kernel<<<dim3(NE, DOUT / 128), 256>>>(lB);
    xe_round_kernel<<<T_TOK / 4, 256>>>(x);
    lora_inter_kernel<<<MAX_TILES, 256>>>(x, adap, lA, lscale);
    main_gemm_kernel<<<dim3(DOUT / BN, MAX_TILES), 256, DSMEM_BYTES>>>(out);
}

// round 8
// speedup vs baseline: 3.1404x; 1.0126x over previous
#include <cuda_runtime.h>
#include <cuda_fp16.h>
#include <cstdint>

#define T_TOK 16384
#define NE    8
#define DIN   1024
#define DOUT  1024
#define NA    8
#define RANK  16
#define BM    128
#define BN    128
#define BK    64                    // halfs per K-chunk (128 bytes)
#define KLORA (NA * RANK)           // 128
#define KEXT  (DIN + KLORA)         // 1152
#define NCHUNK (KEXT / BK)          // 18
#define MAX_TILES 144
#define RSTRIDE 72                  // smem row stride in halfs (64 + 8 pad, 144B)
#define ABY   (BM * RSTRIDE * 2)    // 18432 bytes per buffer
#define DSMEM_BYTES (4 * ABY)       // A0,A1,B0,B1 = 73728 (2 CTAs/SM)

// ---------------- device scratch (static, no allocations) ----------------
__device__ __align__(256) __half g_xe[(size_t)T_TOK * KEXT];     // 37.7 MB [rn(x) | spread scaled inter]
__device__ __align__(256) __half g_wt[(size_t)NE * DOUT * KEXT]; // 18.9 MB [e][n][k]: rn(W^T) | rn(lora_B)

// ---------------- helpers ----------------
__device__ __forceinline__ uint32_t smem_u32(const void* p) {
    uint32_t a;
    asm("{ .reg .u64 t; cvta.to.shared.u64 t, %1; cvt.u32.u64 %0, t; }" : "=r"(a) : "l"(p));
    return a;
}
__device__ __forceinline__ void cp_async16(uint32_t dst, const void* src) {
    asm volatile("cp.async.cg.shared.global [%0], [%1], 16;"
                 :: "r"(dst), "l"(src) : "memory");
}
__device__ __forceinline__ void cp_async16p(uint32_t dst, const void* src, int srcsize) {
    asm volatile("cp.async.cg.shared.global [%0], [%1], 16, %2;"
                 :: "r"(dst), "l"(src), "r"(srcsize) : "memory");
}
__device__ __forceinline__ void ldsm_x4(uint32_t* r, uint32_t addr) {
    asm volatile("ldmatrix.sync.aligned.m8n8.x4.shared.b16 {%0,%1,%2,%3}, [%4];"
                 : "=r"(r[0]), "=r"(r[1]), "=r"(r[2]), "=r"(r[3]) : "r"(addr));
}

// Derive this block's row-tile from group_sizes (replaces setup_kernel).
// Returns false if tile_id is beyond the last tile.
__device__ __forceinline__ bool tile_lookup(const int* __restrict__ gs, int tile_id,
                                            int& row0, int& e, int& rows) {
    int cnt = 0, off = 0;
#pragma unroll
    for (int ee = 0; ee < NE; ee++) {
        int gsz = gs[ee];
        int nt  = (gsz + BM - 1) / BM;
        if (tile_id < cnt + nt) {
            int local = tile_id - cnt;
            row0 = off + local * BM;
            e    = ee;
            rows = min(BM, gsz - local * BM);
            return true;
        }
        cnt += nt;
        off += gsz;
    }
    return false;
}

// ---------------- kernel 1: W transpose + Bext fill (fused) ----------------
// grid: (DIN/64 + 1, DOUT/32, NE). x == DIN/64 handles the lora_B extension.
__global__ __launch_bounds__(256) void prep_w_kernel(const float* __restrict__ wgt,
                                                     const float* __restrict__ lB) {
    int e  = blockIdx.z;
    int n0 = blockIdx.y * 32;
    int tx = threadIdx.x;          // 32
    int ty = threadIdx.y;          // 8

    if (blockIdx.x == DIN / 64) {
        // Bext: g_wt[e][n0+n][1024 + a*16+r] = rn(lora_B[a][e][r][n0+n])
        int tid = ty * 32 + tx;
        for (int f = tid; f < 32 * KLORA; f += 256) {
            int n = f >> 7;
            int j = f & 127;
            int a = j >> 4, r = j & 15;
            g_wt[((size_t)e * DOUT + n0 + n) * KEXT + DIN + j] =
                __float2half_rn(lB[(((size_t)a * NE + e) * RANK + r) * DOUT + n0 + n]);
        }
        return;
    }

    __shared__ float tile[64][33];
    int k0 = blockIdx.x * 64;
#pragma unroll
    for (int i = 0; i < 64; i += 8)
        tile[i + ty][tx] = wgt[((size_t)e * DIN + k0 + i + ty) * DOUT + n0 + tx];
    __syncthreads();
#pragma unroll
    for (int nn = 0; nn < 4; nn++) {               // n = ty + nn*8
        int n = nn * 8 + ty;
        __half2 h = __floats2half2_rn(tile[tx * 2][n], tile[tx * 2 + 1][n]);
        *(__half2*)&g_wt[((size_t)e * DOUT + n0 + n) * KEXT + k0 + tx * 2] = h;
    }
}

// ---------------- kernel 2: lora_inter + x fp16 conversion (fused) ----------------
// Writes g_xe[:, 0:1024] = rn(x) while streaming x for the A-projection, then
// g_xe[:, 1024:1152] = spread(scale * (x @ lora_A)).
__global__ __launch_bounds__(256) void lora_inter_kernel(
    const float* __restrict__ x,
    const int*   __restrict__ gs,
    const int*   __restrict__ adap,
    const float* __restrict__ lA,
    const float* __restrict__ lscale)
{
    __shared__ float xs[BM][33];
    __shared__ float as_[NA][32][RANK];

    int row0, e, rows;
    if (!tile_lookup(gs, blockIdx.x, row0, e, rows)) return;

    int tid  = threadIdx.x;
    int r    = tid & 15;
    int tg   = tid >> 4;

    int   aj[8];
    float acc[8];
#pragma unroll
    for (int j = 0; j < 8; j++) {
        int tok = tg + j * 16;
        aj[j]  = (tok < rows) ? adap[row0 + tok] : 0;
        acc[j] = 0.f;
    }

    for (int k0 = 0; k0 < DIN; k0 += 32) {
#pragma unroll
        for (int it = 0; it < 4; it++) {
            int flat = (tid + it * 256) * 4;
            int tok  = flat >> 5;
            int kk   = flat & 31;
            float4 v = make_float4(0.f, 0.f, 0.f, 0.f);
            if (tok < rows) {
                v = *(const float4*)&x[(size_t)(row0 + tok) * DIN + k0 + kk];
                // fused fp16 conversion (replaces xe_round_kernel)
                __half2* dst = (__half2*)&g_xe[(size_t)(row0 + tok) * KEXT + k0 + kk];
                dst[0] = __floats2half2_rn(v.x, v.y);
                dst[1] = __floats2half2_rn(v.z, v.w);
            }
            xs[tok][kk] = v.x; xs[tok][kk + 1] = v.y;
            xs[tok][kk + 2] = v.z; xs[tok][kk + 3] = v.w;
        }
#pragma unroll
        for (int it = 0; it < 4; it++) {
            int flat = (tid + it * 256) * 4;
            int a    = flat >> 9;
            int rem  = flat & 511;
            int kk   = rem >> 4;
            int rr   = rem & 15;
            float4 v = *(const float4*)&lA[((size_t)(a * NE + e) * DIN + k0 + kk) * RANK + rr];
            *(float4*)&as_[a][kk][rr] = v;
        }
        __syncthreads();
#pragma unroll
        for (int kk = 0; kk < 32; kk++)
#pragma unroll
            for (int j = 0; j < 8; j++)
                acc[j] += xs[tg + j * 16][kk] * as_[aj[j]][kk][r];
        __syncthreads();
    }

#pragma unroll
    for (int j = 0; j < 8; j++) {
        int tok = tg + j * 16;
        if (tok < rows) {
            __half hv = __float2half_rn(acc[j] * lscale[aj[j]]);
            __half hz = __float2half_rn(0.f);
            __half* dst = g_xe + (size_t)(row0 + tok) * KEXT + DIN + r;
#pragma unroll
            for (int a = 0; a < NA; a++) dst[a * RANK] = (a == aj[j]) ? hv : hz;
        }
    }
}

// ---------------- kernel 3: fp16 mma.sync GEMM, 128x128 tile, K = 1152 ----------------
__global__ __launch_bounds__(256, 2) void main_gemm_kernel(const int* __restrict__ gs,
                                                           float* __restrict__ out) {
    extern __shared__ char sm[];
    int row0, e, rows;
    if (!tile_lookup(gs, blockIdx.y, row0, e, rows)) return;

    int col0 = blockIdx.x * BN;
    int tid  = threadIdx.x;
    int lane = tid & 31;
    int wid  = tid >> 5;
    int wm   = (wid & 3) * 32;      // warp row base (4 warps in M)
    int wn   = (wid >> 2) * 64;     // warp col base (2 warps in N)
    int gi   = lane >> 2;           // groupID
    int ti   = lane & 3;            // threadID_in_group

    uint32_t sbase = smem_u32(sm);
    const __half* arow = g_xe + (size_t)row0 * KEXT;
    const __half* brow = g_wt + ((size_t)e * DOUT + col0) * KEXT;

    uint32_t aoff[2];
#pragma unroll
    for (int i = 0; i < 2; i++)
        aoff[i] = (uint32_t)((wm + i * 16 + (lane & 15)) * RSTRIDE + (lane >> 4) * 8) * 2;
    uint32_t boff[4];
#pragma unroll
    for (int p = 0; p < 4; p++)
        boff[p] = (uint32_t)((wn + p * 16 + ((lane >> 4) << 3) + (lane & 7)) * RSTRIDE
                             + (((lane >> 3) & 1) << 3)) * 2;

    float acc[2][8][4];
#pragma unroll
    for (int i = 0; i < 2; i++)
#pragma unroll
        for (int j = 0; j < 8; j++)
#pragma unroll
            for (int q = 0; q < 4; q++) acc[i][j][q] = 0.f;

    bool full = (rows == BM);
    auto load_chunk = [&](int c) {
        uint32_t ab = sbase + (c & 1) * ABY;
        uint32_t bb = sbase + 2 * ABY + (c & 1) * ABY;
        if (full) {
#pragma unroll
            for (int it = 0; it < 4; it++) {
                int f = tid + it * 256;
                int m = f >> 3, q = f & 7;
                cp_async16(ab + m * (RSTRIDE * 2) + q * 16,
                           arow + (size_t)m * KEXT + c * BK + q * 8);
                cp_async16(bb + m * (RSTRIDE * 2) + q * 16,
                           brow + (size_t)m * KEXT + c * BK + q * 8);
            }
        } else {
#pragma unroll
            for (int it = 0; it < 4; it++) {
                int f = tid + it * 256;
                int m = f >> 3, q = f & 7;
                cp_async16p(ab + m * (RSTRIDE * 2) + q * 16,
                            arow + (size_t)m * KEXT + c * BK + q * 8,
                            (m < rows) ? 16 : 0);
                cp_async16(bb + m * (RSTRIDE * 2) + q * 16,
                           brow + (size_t)m * KEXT + c * BK + q * 8);
            }
        }
    };

    load_chunk(0);
    asm volatile("cp.async.commit_group;" ::: "memory");

    for (int c = 0; c < NCHUNK; c++) {
        asm volatile("cp.async.wait_group 0;" ::: "memory");
        __syncthreads();

        if (c + 1 < NCHUNK) {
            load_chunk(c + 1);
            asm volatile("cp.async.commit_group;" ::: "memory");
        }

        uint32_t abase = sbase + (c & 1) * ABY;
        uint32_t bbase = sbase + 2 * ABY + (c & 1) * ABY;

#pragma unroll
        for (int t = 0; t < 4; t++) {
            uint32_t a[2][4], b[4][4];
#pragma unroll
            for (int i = 0; i < 2; i++) ldsm_x4(a[i], abase + aoff[i] + t * 32);
#pragma unroll
            for (int p = 0; p < 4; p++) ldsm_x4(b[p], bbase + boff[p] + t * 32);
#pragma unroll
            for (int i = 0; i < 2; i++)
#pragma unroll
                for (int j = 0; j < 8; j++) {
                    float* d = acc[i][j];
                    asm volatile(
                        "mma.sync.aligned.m16n8k16.row.col.f32.f16.f16.f32 "
                        "{%0,%1,%2,%3}, {%4,%5,%6,%7}, {%8,%9}, {%0,%1,%2,%3};"
                        : "+f"(d[0]), "+f"(d[1]), "+f"(d[2]), "+f"(d[3])
                        : "r"(a[i][0]), "r"(a[i][1]), "r"(a[i][2]), "r"(a[i][3]),
                          "r"(b[j >> 1][(j & 1) * 2]), "r"(b[j >> 1][(j & 1) * 2 + 1]));
                }
        }
    }

    // -------- epilogue: registers -> gmem --------
    float* obase = out + (size_t)row0 * DOUT + col0;
#pragma unroll
    for (int i = 0; i < 2; i++) {
        int r1 = wm + i * 16 + gi;
#pragma unroll
        for (int j = 0; j < 8; j++) {
            int cn = wn + j * 8 + ti * 2;
            if (r1 < rows)
                *(float2*)(obase + (size_t)r1 * DOUT + cn) =
                    make_float2(acc[i][j][0], acc[i][j][1]);
            if (r1 + 8 < rows)
                *(float2*)(obase + (size_t)(r1 + 8) * DOUT + cn) =
                    make_float2(acc[i][j][2], acc[i][j][3]);
        }
    }
}

// ---------------- launch ----------------
extern "C" void kernel_launch(void* const* d_in, const int* in_sizes, int n_in,
                              void* d_out, int out_size) {
    const float* x      = (const float*)d_in[0];
    const int*   gs     = (const int*)  d_in[1];
    const int*   adap   = (const int*)  d_in[2];
    const float* wgt    = (const float*)d_in[3];
    const float* lA     = (const float*)d_in[4];
    const float* lB     = (const float*)d_in[5];
    const float* lscale = (const float*)d_in[6];
    float*       out    = (float*)d_out;

    cudaFuncSetAttribute(main_gemm_kernel,
                         cudaFuncAttributeMaxDynamicSharedMemorySize, DSMEM_BYTES);

    prep_w_kernel<<<dim3(DIN / 64 + 1, DOUT / 32, NE), dim3(32, 8)>>>(wgt, lB);
    lora_inter_kernel<<<MAX_TILES, 256>>>(x, gs, adap, lA, lscale);
    main_gemm_kernel<<<dim3(DOUT / BN, MAX_TILES), 256, DSMEM_BYTES>>>(gs, out);
}